// round 1
// baseline (speedup 1.0000x reference)
#include <cuda_runtime.h>
#include <cuda_bf16.h>

// ---------------------------------------------------------------------------
// Problem constants
// ---------------------------------------------------------------------------
#define B_  16
#define S_  1024
#define DIN 1024
#define DH  4096
#define DOUT 1024
#define TOK (B_ * S_)          // 16384 rows
#define EPS 1e-5f

// ---------------------------------------------------------------------------
// Scratch buffers (static device globals; no allocation at runtime)
// ---------------------------------------------------------------------------
__device__ float g_big [ (long long)TOK * DH ];    // h, later ffn hidden (256 MB)
__device__ float g_xln [ (long long)TOK * DIN ];
__device__ float g_xp  [ (long long)TOK * DOUT ];
__device__ float g_q   [ (long long)TOK * DOUT ];  // later reused for ffn out
__device__ float g_k   [ (long long)TOK * DOUT ];
__device__ float g_v   [ (long long)TOK * DOUT ];
__device__ float g_sc  [ (long long)B_ * S_ * S_ ];
__device__ float g_ao  [ (long long)TOK * DOUT ];
__device__ float g_x1  [ (long long)TOK * DOUT ];
__device__ float g_x2  [ (long long)TOK * DOUT ];

// ---------------------------------------------------------------------------
// Warp/block reduction helpers
// ---------------------------------------------------------------------------
__device__ __forceinline__ float warp_sum(float v) {
    #pragma unroll
    for (int o = 16; o > 0; o >>= 1) v += __shfl_xor_sync(0xFFFFFFFFu, v, o);
    return v;
}
__device__ __forceinline__ float warp_max(float v) {
    #pragma unroll
    for (int o = 16; o > 0; o >>= 1) v = fmaxf(v, __shfl_xor_sync(0xFFFFFFFFu, v, o));
    return v;
}

// ---------------------------------------------------------------------------
// GEMM: C[M,N] = act( A[M,K] @ op(B) + bias )
// TRANS_B=0: B is [K,N] row-major.  TRANS_B=1: B is [N,K] row-major (C=A·B^T)
// EPI: 0 none, 1 relu, 2 clip(p0,p1)
// Block 256 threads, tile 128x128x16, 8x8 per thread.
// All dims assumed multiples of tile sizes (true for this problem).
// ---------------------------------------------------------------------------
#define BM 128
#define BN 128
#define BKK 16
#define TM 8
#define TN 8

template<int TRANS_B, int EPI>
__global__ __launch_bounds__(256, 2)
void gemm_kernel(const float* __restrict__ A, const float* __restrict__ Bm,
                 const float* __restrict__ bias, float* __restrict__ C,
                 int M, int N, int K,
                 long long sA, long long sB, long long sC,
                 float p0, float p1)
{
    __shared__ float As[BKK][BM];
    __shared__ float Bs[BKK][BN];

    A  += (long long)blockIdx.z * sA;
    Bm += (long long)blockIdx.z * sB;
    C  += (long long)blockIdx.z * sC;

    const int tid = threadIdx.x;
    const int tx = tid & 15;         // 0..15 -> N direction
    const int ty = tid >> 4;         // 0..15 -> M direction
    const int row0 = blockIdx.y * BM;
    const int col0 = blockIdx.x * BN;

    float acc[TM][TN];
    #pragma unroll
    for (int i = 0; i < TM; i++)
        #pragma unroll
        for (int j = 0; j < TN; j++) acc[i][j] = 0.f;

    for (int k0 = 0; k0 < K; k0 += BKK) {
        // ---- load A tile (BM x BKK), store transposed: As[k][m]
        #pragma unroll
        for (int i = 0; i < 2; i++) {
            int lin = tid + i * 256;          // 0..511
            int r  = lin >> 2;                // 0..127
            int c4 = lin & 3;                 // 0..3 (float4 within 16 cols)
            float4 v = *(const float4*)(A + (long long)(row0 + r) * K + k0 + c4 * 4);
            As[c4*4+0][r] = v.x; As[c4*4+1][r] = v.y;
            As[c4*4+2][r] = v.z; As[c4*4+3][r] = v.w;
        }
        // ---- load B tile -> Bs[k][n]
        if (TRANS_B == 0) {
            #pragma unroll
            for (int i = 0; i < 2; i++) {
                int lin = tid + i * 256;
                int r  = lin >> 5;            // 0..15
                int c4 = lin & 31;            // 0..31
                float4 v = *(const float4*)(Bm + (long long)(k0 + r) * N + col0 + c4 * 4);
                *(float4*)(&Bs[r][c4 * 4]) = v;
            }
        } else {
            #pragma unroll
            for (int i = 0; i < 2; i++) {
                int lin = tid + i * 256;
                int n  = lin >> 2;            // 0..127
                int c4 = lin & 3;             // 0..3
                float4 v = *(const float4*)(Bm + (long long)(col0 + n) * K + k0 + c4 * 4);
                Bs[c4*4+0][n] = v.x; Bs[c4*4+1][n] = v.y;
                Bs[c4*4+2][n] = v.z; Bs[c4*4+3][n] = v.w;
            }
        }
        __syncthreads();

        #pragma unroll
        for (int kk = 0; kk < BKK; kk++) {
            float ra[TM], rb[TN];
            float4 a0 = *(const float4*)(&As[kk][ty * TM]);
            float4 a1 = *(const float4*)(&As[kk][ty * TM + 4]);
            ra[0]=a0.x; ra[1]=a0.y; ra[2]=a0.z; ra[3]=a0.w;
            ra[4]=a1.x; ra[5]=a1.y; ra[6]=a1.z; ra[7]=a1.w;
            float4 b0 = *(const float4*)(&Bs[kk][tx * TN]);
            float4 b1 = *(const float4*)(&Bs[kk][tx * TN + 4]);
            rb[0]=b0.x; rb[1]=b0.y; rb[2]=b0.z; rb[3]=b0.w;
            rb[4]=b1.x; rb[5]=b1.y; rb[6]=b1.z; rb[7]=b1.w;
            #pragma unroll
            for (int i = 0; i < TM; i++)
                #pragma unroll
                for (int j = 0; j < TN; j++)
                    acc[i][j] = fmaf(ra[i], rb[j], acc[i][j]);
        }
        __syncthreads();
    }

    // ---- epilogue
    #pragma unroll
    for (int i = 0; i < TM; i++) {
        long long r = row0 + ty * TM + i;
        #pragma unroll
        for (int j = 0; j < TN; j += 4) {
            int c = col0 + tx * TN + j;
            float4 v;
            v.x = acc[i][j+0]; v.y = acc[i][j+1];
            v.z = acc[i][j+2]; v.w = acc[i][j+3];
            if (bias) {
                v.x += bias[c+0]; v.y += bias[c+1];
                v.z += bias[c+2]; v.w += bias[c+3];
            }
            if (EPI == 1) {
                v.x = fmaxf(v.x, 0.f); v.y = fmaxf(v.y, 0.f);
                v.z = fmaxf(v.z, 0.f); v.w = fmaxf(v.w, 0.f);
            } else if (EPI == 2) {
                v.x = fminf(fmaxf(v.x, p0), p1); v.y = fminf(fmaxf(v.y, p0), p1);
                v.z = fminf(fmaxf(v.z, p0), p1); v.w = fminf(fmaxf(v.w, p0), p1);
            }
            *(float4*)(C + r * N + c) = v;
        }
    }
}

// ---------------------------------------------------------------------------
// LayerNorm: out[row] = LN(X[row] (+ R[row])) * g + b     (D = 1024 fixed)
// One 256-thread block per row, 4 elements (one float4) per thread.
// ---------------------------------------------------------------------------
__global__ __launch_bounds__(256)
void ln_kernel(const float* __restrict__ X, const float* __restrict__ R,
               const float* __restrict__ g, const float* __restrict__ bta,
               float* __restrict__ out)
{
    const int D = 1024;
    long long base = (long long)blockIdx.x * D;
    int t = threadIdx.x;

    float4 xv = *(const float4*)(X + base + t * 4);
    if (R) {
        float4 rv = *(const float4*)(R + base + t * 4);
        xv.x += rv.x; xv.y += rv.y; xv.z += rv.z; xv.w += rv.w;
    }
    float s  = xv.x + xv.y + xv.z + xv.w;
    float ss = xv.x*xv.x + xv.y*xv.y + xv.z*xv.z + xv.w*xv.w;

    __shared__ float sh[16];
    int w = t >> 5, l = t & 31;
    s  = warp_sum(s);
    ss = warp_sum(ss);
    if (l == 0) { sh[w] = s; sh[8 + w] = ss; }
    __syncthreads();
    if (t < 32) {
        float a  = (l < 8) ? sh[l]     : 0.f;
        float b2 = (l < 8) ? sh[8 + l] : 0.f;
        a  = warp_sum(a);
        b2 = warp_sum(b2);
        if (l == 0) { sh[0] = a; sh[1] = b2; }
    }
    __syncthreads();

    float mu  = sh[0] * (1.f / 1024.f);
    float var = sh[1] * (1.f / 1024.f) - mu * mu;
    var = fmaxf(var, 0.f);
    float rs = rsqrtf(var + EPS);

    float4 gv = *(const float4*)(g   + t * 4);
    float4 bv = *(const float4*)(bta + t * 4);
    float4 o;
    o.x = (xv.x - mu) * rs * gv.x + bv.x;
    o.y = (xv.y - mu) * rs * gv.y + bv.y;
    o.z = (xv.z - mu) * rs * gv.z + bv.z;
    o.w = (xv.w - mu) * rs * gv.w + bv.w;
    *(float4*)(out + base + t * 4) = o;
}

// ---------------------------------------------------------------------------
// Masked softmax over scores[b, s, :]: val = mask[b,t] ? sc*scale : -1e9
// One 256-thread block per (b, s) row; S = 1024.
// ---------------------------------------------------------------------------
__global__ __launch_bounds__(256)
void softmax_kernel(float* __restrict__ scores, const int* __restrict__ mask,
                    const float* __restrict__ scale)
{
    const int S = 1024;
    int b = blockIdx.y;
    long long base = (((long long)b * S) + blockIdx.x) * S;
    int t = threadIdx.x;
    float sc = scale[0];

    float4 v = *(float4*)(scores + base + t * 4);
    const int4 mv = *(const int4*)(mask + b * S + t * 4);
    float e0 = (mv.x != 0) ? v.x * sc : -1e9f;
    float e1 = (mv.y != 0) ? v.y * sc : -1e9f;
    float e2 = (mv.z != 0) ? v.z * sc : -1e9f;
    float e3 = (mv.w != 0) ? v.w * sc : -1e9f;

    __shared__ float sh[8];
    int w = t >> 5, l = t & 31;

    float m = fmaxf(fmaxf(e0, e1), fmaxf(e2, e3));
    m = warp_max(m);
    if (l == 0) sh[w] = m;
    __syncthreads();
    if (t < 32) {
        float a = (l < 8) ? sh[l] : -3.4e38f;
        a = warp_max(a);
        if (l == 0) sh[0] = a;
    }
    __syncthreads();
    m = sh[0];
    __syncthreads();

    float x0 = __expf(e0 - m), x1 = __expf(e1 - m);
    float x2 = __expf(e2 - m), x3 = __expf(e3 - m);
    float sum = x0 + x1 + x2 + x3;
    sum = warp_sum(sum);
    if (l == 0) sh[w] = sum;
    __syncthreads();
    if (t < 32) {
        float a = (l < 8) ? sh[l] : 0.f;
        a = warp_sum(a);
        if (l == 0) sh[0] = a;
    }
    __syncthreads();
    float inv = 1.f / sh[0];

    float4 o;
    o.x = x0 * inv; o.y = x1 * inv; o.z = x2 * inv; o.w = x3 * inv;
    *(float4*)(scores + base + t * 4) = o;
}

// ---------------------------------------------------------------------------
// Launch
// ---------------------------------------------------------------------------
extern "C" void kernel_launch(void* const* d_in, const int* in_sizes, int n_in,
                              void* d_out, int out_size)
{
    const float* x       = (const float*)d_in[0];
    const int*   mask    = (const int*)  d_in[1];
    const float* ln_in_g = (const float*)d_in[2];
    const float* ln_in_b = (const float*)d_in[3];
    const float* W_mlp   = (const float*)d_in[4];
    const float* b_mlp   = (const float*)d_in[5];
    const float* W_proj  = (const float*)d_in[6];
    const float* b_proj  = (const float*)d_in[7];
    const float* scale   = (const float*)d_in[8];
    const float* Wq      = (const float*)d_in[9];
    const float* bq      = (const float*)d_in[10];
    const float* Wk      = (const float*)d_in[11];
    const float* bk      = (const float*)d_in[12];
    const float* Wv      = (const float*)d_in[13];
    const float* bv      = (const float*)d_in[14];
    const float* ln1_g   = (const float*)d_in[15];
    const float* ln1_b   = (const float*)d_in[16];
    const float* W_f1    = (const float*)d_in[17];
    const float* b_f1    = (const float*)d_in[18];
    const float* W_f2    = (const float*)d_in[19];
    const float* b_f2    = (const float*)d_in[20];
    const float* ln2_g   = (const float*)d_in[21];
    const float* ln2_b   = (const float*)d_in[22];
    const float* lno_g   = (const float*)d_in[23];
    const float* lno_b   = (const float*)d_in[24];
    float* out = (float*)d_out;

    float *big, *xln, *xp, *q, *k, *v, *sc, *ao, *x1, *x2;
    cudaGetSymbolAddress((void**)&big, g_big);
    cudaGetSymbolAddress((void**)&xln, g_xln);
    cudaGetSymbolAddress((void**)&xp,  g_xp);
    cudaGetSymbolAddress((void**)&q,   g_q);
    cudaGetSymbolAddress((void**)&k,   g_k);
    cudaGetSymbolAddress((void**)&v,   g_v);
    cudaGetSymbolAddress((void**)&sc,  g_sc);
    cudaGetSymbolAddress((void**)&ao,  g_ao);
    cudaGetSymbolAddress((void**)&x1,  g_x1);
    cudaGetSymbolAddress((void**)&x2,  g_x2);

    const dim3 blk(256);

    // 1. x_ln = LN(x)
    ln_kernel<<<TOK, blk>>>(x, nullptr, ln_in_g, ln_in_b, xln);

    // 2. h = relu(x_ln @ W_mlp + b_mlp)   [TOK, DH]
    {
        dim3 grid(DH / BN, TOK / BM, 1);
        gemm_kernel<0, 1><<<grid, blk>>>(xln, W_mlp, b_mlp, big,
                                         TOK, DH, DIN, 0, 0, 0, 0.f, 0.f);
    }
    // 3. xp = clip(h @ W_proj + b_proj, -100, 100)   [TOK, DOUT]
    {
        dim3 grid(DOUT / BN, TOK / BM, 1);
        gemm_kernel<0, 2><<<grid, blk>>>(big, W_proj, b_proj, xp,
                                         TOK, DOUT, DH, 0, 0, 0, -100.f, 100.f);
    }
    // 4. q/k/v projections
    {
        dim3 grid(DOUT / BN, TOK / BM, 1);
        gemm_kernel<0, 0><<<grid, blk>>>(xp, Wq, bq, q, TOK, DOUT, DOUT, 0, 0, 0, 0.f, 0.f);
        gemm_kernel<0, 0><<<grid, blk>>>(xp, Wk, bk, k, TOK, DOUT, DOUT, 0, 0, 0, 0.f, 0.f);
        gemm_kernel<0, 0><<<grid, blk>>>(xp, Wv, bv, v, TOK, DOUT, DOUT, 0, 0, 0, 0.f, 0.f);
    }
    // 5. scores[b] = q[b] @ k[b]^T     (batched NT)
    {
        dim3 grid(S_ / BN, S_ / BM, B_);
        gemm_kernel<1, 0><<<grid, blk>>>(q, k, nullptr, sc,
                                         S_, S_, DOUT,
                                         (long long)S_ * DOUT, (long long)S_ * DOUT,
                                         (long long)S_ * S_, 0.f, 0.f);
    }
    // 6. masked softmax (applies * scale and mask)
    {
        dim3 grid(S_, B_);
        softmax_kernel<<<grid, blk>>>(sc, mask, scale);
    }
    // 7. ao[b] = attn[b] @ v[b]        (batched NN)
    {
        dim3 grid(DOUT / BN, S_ / BM, B_);
        gemm_kernel<0, 0><<<grid, blk>>>(sc, v, nullptr, ao,
                                         S_, DOUT, S_,
                                         (long long)S_ * S_, (long long)S_ * DOUT,
                                         (long long)S_ * DOUT, 0.f, 0.f);
    }
    // 8. x1 = LN(xp + ao)
    ln_kernel<<<TOK, blk>>>(xp, ao, ln1_g, ln1_b, x1);

    // 9. ffn_h = relu(x1 @ W_f1 + b_f1)   [TOK, DH]
    {
        dim3 grid(DH / BN, TOK / BM, 1);
        gemm_kernel<0, 1><<<grid, blk>>>(x1, W_f1, b_f1, big,
                                         TOK, DH, DOUT, 0, 0, 0, 0.f, 0.f);
    }
    // 10. ffn_o = ffn_h @ W_f2 + b_f2   (reuse q buffer)
    {
        dim3 grid(DOUT / BN, TOK / BM, 1);
        gemm_kernel<0, 0><<<grid, blk>>>(big, W_f2, b_f2, q,
                                         TOK, DOUT, DH, 0, 0, 0, 0.f, 0.f);
    }
    // 11. x2 = LN(x1 + ffn_o)
    ln_kernel<<<TOK, blk>>>(x1, q, ln2_g, ln2_b, x2);

    // 12. out = LN(x2)
    ln_kernel<<<TOK, blk>>>(x2, nullptr, lno_g, lno_b, out);
}

// round 5
// speedup vs baseline: 2.8678x; 2.8678x over previous
#include <cuda_runtime.h>
#include <cuda_bf16.h>
#include <cstdint>

// ---------------------------------------------------------------------------
// Problem constants
// ---------------------------------------------------------------------------
#define B_  16
#define S_  1024
#define DIN 1024
#define DH  4096
#define DOUT 1024
#define TOK (B_ * S_)          // 16384 rows
#define EPS 1e-5f

// ---------------------------------------------------------------------------
// Helpers
// ---------------------------------------------------------------------------
__device__ __forceinline__ uint32_t smem_u32(const void* p) {
    uint32_t a;
    asm("{ .reg .u64 t; cvta.to.shared.u64 t, %1; cvt.u32.u64 %0, t; }" : "=r"(a) : "l"(p));
    return a;
}

__device__ __forceinline__ void ldsm4(uint32_t& r0, uint32_t& r1, uint32_t& r2, uint32_t& r3,
                                      uint32_t addr) {
    asm volatile("ldmatrix.sync.aligned.m8n8.x4.shared.b16 {%0,%1,%2,%3}, [%4];"
                 : "=r"(r0), "=r"(r1), "=r"(r2), "=r"(r3) : "r"(addr));
}
__device__ __forceinline__ void mma16816(float* d, const uint32_t* a, const uint32_t* b) {
    asm volatile(
        "mma.sync.aligned.m16n8k16.row.col.f32.bf16.bf16.f32 "
        "{%0,%1,%2,%3}, {%4,%5,%6,%7}, {%8,%9}, {%0,%1,%2,%3};"
        : "+f"(d[0]), "+f"(d[1]), "+f"(d[2]), "+f"(d[3])
        : "r"(a[0]), "r"(a[1]), "r"(a[2]), "r"(a[3]), "r"(b[0]), "r"(b[1]));
}

__device__ __forceinline__ void bf16split(float v, __nv_bfloat16& h, __nv_bfloat16& l) {
    h = __float2bfloat16(v);
    l = __float2bfloat16(v - __bfloat162float(h));
}

__device__ __forceinline__ float warp_sum(float v) {
    #pragma unroll
    for (int o = 16; o > 0; o >>= 1) v += __shfl_xor_sync(0xFFFFFFFFu, v, o);
    return v;
}
__device__ __forceinline__ float warp_max(float v) {
    #pragma unroll
    for (int o = 16; o > 0; o >>= 1) v = fmaxf(v, __shfl_xor_sync(0xFFFFFFFFu, v, o));
    return v;
}

// ---------------------------------------------------------------------------
// Scratch buffers (static device globals; no runtime allocation)
// ---------------------------------------------------------------------------
#define NTOKD ((long long)TOK * DOUT)   // 16.8M
#define NTOKH ((long long)TOK * DH)     // 67.1M

__device__ __align__(1024) float g_xp [NTOKD];
__device__ __align__(1024) float g_v  [NTOKD];   // reused as ffn_out later
__device__ __align__(1024) float g_sc [NTOKD];   // scores [B,S,S] = 16M
__device__ __align__(1024) float g_ao [NTOKD];
__device__ __align__(1024) float g_x1 [NTOKD];

__device__ __align__(1024) __nv_bfloat16 g_xln_h[NTOKD], g_xln_l[NTOKD];
__device__ __align__(1024) __nv_bfloat16 g_big_h[NTOKH], g_big_l[NTOKH];
__device__ __align__(1024) __nv_bfloat16 g_xp_h [NTOKD], g_xp_l [NTOKD];
__device__ __align__(1024) __nv_bfloat16 g_q_h  [NTOKD], g_q_l  [NTOKD];
__device__ __align__(1024) __nv_bfloat16 g_k_h  [NTOKD], g_k_l  [NTOKD];
__device__ __align__(1024) __nv_bfloat16 g_vt_h [NTOKD], g_vt_l [NTOKD];
__device__ __align__(1024) __nv_bfloat16 g_at_h [NTOKD], g_at_l [NTOKD];
__device__ __align__(1024) __nv_bfloat16 g_x1_h [NTOKD], g_x1_l [NTOKD];

// transposed weights ([N,K] hi/lo)
__device__ __align__(1024) __nv_bfloat16 g_wmlp_h[(long long)DH*DIN],  g_wmlp_l[(long long)DH*DIN];
__device__ __align__(1024) __nv_bfloat16 g_wprj_h[(long long)DOUT*DH], g_wprj_l[(long long)DOUT*DH];
__device__ __align__(1024) __nv_bfloat16 g_wq_h[(long long)DOUT*DOUT], g_wq_l[(long long)DOUT*DOUT];
__device__ __align__(1024) __nv_bfloat16 g_wk_h[(long long)DOUT*DOUT], g_wk_l[(long long)DOUT*DOUT];
__device__ __align__(1024) __nv_bfloat16 g_wv_h[(long long)DOUT*DOUT], g_wv_l[(long long)DOUT*DOUT];
__device__ __align__(1024) __nv_bfloat16 g_wf1_h[(long long)DH*DOUT],  g_wf1_l[(long long)DH*DOUT];
__device__ __align__(1024) __nv_bfloat16 g_wf2_h[(long long)DOUT*DH],  g_wf2_l[(long long)DOUT*DH];

// ---------------------------------------------------------------------------
// mma.sync GEMM:  C[M,N](+bias,act) = A[M,K] @ B^T   (B stored [N,K])
// A,B as bf16 hi/lo pairs; D = Ah*Bh + Ah*Bl + Al*Bh, fp32 accum.
// CTA tile 128x128x64, 8 warps (warp tile 32x64), 3-stage cp.async.
// Smem per stage: Ah|Al|Bh|Bl 16KB each = 64KB; 3 stages = 192KB.
// SW128 swizzle: 128B rows (64 bf16 = one K-chunk).
// B fragments use NON-trans ldmatrix: [N,K] K-contiguous rows addressed by n
// yield exactly the m16n8k16 B layout (thread t: n=t/4, k-pair=(t%4)*2).
// ---------------------------------------------------------------------------
#define GBM 128
#define GBN 128
#define GBK 64
#define STAGE_BYTES 65536
#define SMEM_DYN (3 * STAGE_BYTES)

#define SWZ(off) ((off) ^ (((off) >> 3) & 0x70u))

__global__ __launch_bounds__(256, 1)
void tc_gemm(const __nv_bfloat16* __restrict__ Ah, const __nv_bfloat16* __restrict__ Al,
             const __nv_bfloat16* __restrict__ Bh, const __nv_bfloat16* __restrict__ Bl,
             const float* __restrict__ bias, float* __restrict__ C,
             __nv_bfloat16* __restrict__ Ch, __nv_bfloat16* __restrict__ Cl,
             int K, int N, long long sA, long long sB, long long sC,
             int epi, float clo, float chi)
{
    extern __shared__ char dyn_smem[];
    const uint32_t smemBase = smem_u32(dyn_smem);

    const int tid  = threadIdx.x;
    const int wid  = tid >> 5;
    const int lane = tid & 31;
    const int wm   = wid & 3;        // 4 warps in M
    const int wn   = wid >> 2;       // 2 warps in N

    Ah += blockIdx.z * sA; Al += blockIdx.z * sA;
    Bh += blockIdx.z * sB; Bl += blockIdx.z * sB;

    const int row0 = blockIdx.y * GBM;
    const int col0 = blockIdx.x * GBN;
    const int NC   = K / GBK;

    float acc[2][8][4];
    #pragma unroll
    for (int i = 0; i < 2; i++)
        #pragma unroll
        for (int j = 0; j < 8; j++)
            #pragma unroll
            for (int e = 0; e < 4; e++) acc[i][j][e] = 0.f;

    // ---- async tile loader: 4096 x 16B per chunk, 16 per thread
    auto load_chunk = [&](int chunk, int stage) {
        if (chunk < NC) {
            const uint32_t sb = smemBase + stage * STAGE_BYTES;
            const int k0 = chunk * GBK;
            #pragma unroll
            for (int i = 0; i < 16; i++) {
                int idx = i * 256 + tid;          // 0..4095
                int t   = idx >> 10;              // 0:Ah 1:Al 2:Bh 3:Bl
                int w   = idx & 1023;
                int r   = w >> 3, g = w & 7;
                const __nv_bfloat16* src;
                if (t == 0)      src = Ah + (long long)(row0 + r) * K + k0 + g * 8;
                else if (t == 1) src = Al + (long long)(row0 + r) * K + k0 + g * 8;
                else if (t == 2) src = Bh + (long long)(col0 + r) * K + k0 + g * 8;
                else             src = Bl + (long long)(col0 + r) * K + k0 + g * 8;
                uint32_t off = (uint32_t)(r * 128 + g * 16);
                uint32_t dst = sb + t * 16384 + SWZ(off);
                asm volatile("cp.async.cg.shared.global [%0], [%1], 16;" :: "r"(dst), "l"(src));
            }
        }
        asm volatile("cp.async.commit_group;" ::: "memory");
    };

    load_chunk(0, 0);
    load_chunk(1, 1);
    load_chunk(2, 2);

    const int m0 = wm * 32;
    const int n0 = wn * 64;

    for (int i = 0; i < NC; i++) {
        asm volatile("cp.async.wait_group 2;" ::: "memory");
        __syncthreads();

        const uint32_t sb  = smemBase + (i % 3) * STAGE_BYTES;
        const uint32_t aH  = sb;
        const uint32_t aL  = sb + 16384;
        const uint32_t bH  = sb + 32768;
        const uint32_t bL  = sb + 49152;

        #pragma unroll
        for (int k16 = 0; k16 < 4; k16++) {
            // A fragments (hi & lo) for both 16-row m-frags
            uint32_t ahf[2][4], alf[2][4];
            #pragma unroll
            for (int mf = 0; mf < 2; mf++) {
                int sub = lane >> 3;
                int r = m0 + mf * 16 + (sub & 1) * 8 + (lane & 7);
                int g = k16 * 2 + (sub >> 1);
                uint32_t off = (uint32_t)(r * 128 + g * 16);
                uint32_t sw = SWZ(off);
                ldsm4(ahf[mf][0], ahf[mf][1], ahf[mf][2], ahf[mf][3], aH + sw);
                ldsm4(alf[mf][0], alf[mf][1], alf[mf][2], alf[mf][3], aL + sw);
            }
            // B tiles: 4 x 16 columns; NON-trans ldmatrix on [N,K] rows:
            // group0:(n0-7,kblk0)->b0  group1:(n0-7,kblk1)->b1 (n-frag 0)
            // group2:(n8-15,kblk0)     group3:(n8-15,kblk1)    (n-frag 1)
            #pragma unroll
            for (int nt = 0; nt < 4; nt++) {
                int sub = lane >> 3;
                int r = n0 + nt * 16 + (sub >> 1) * 8 + (lane & 7);
                int g = k16 * 2 + (sub & 1);
                uint32_t off = (uint32_t)(r * 128 + g * 16);
                uint32_t sw = SWZ(off);
                uint32_t bhf[4], blf[4];
                ldsm4(bhf[0], bhf[1], bhf[2], bhf[3], bH + sw);
                ldsm4(blf[0], blf[1], blf[2], blf[3], bL + sw);
                #pragma unroll
                for (int mf = 0; mf < 2; mf++) {
                    #pragma unroll
                    for (int ns = 0; ns < 2; ns++) {
                        float* d = acc[mf][nt * 2 + ns];
                        mma16816(d, ahf[mf], &bhf[ns * 2]);
                        mma16816(d, ahf[mf], &blf[ns * 2]);
                        mma16816(d, alf[mf], &bhf[ns * 2]);
                    }
                }
            }
        }
        __syncthreads();
        load_chunk(i + 3, i % 3);
    }

    // ---- epilogue
    const int rbase = row0 + m0;
    const int cbase = col0 + n0;
    #pragma unroll
    for (int mf = 0; mf < 2; mf++) {
        #pragma unroll
        for (int nf = 0; nf < 8; nf++) {
            int col = cbase + nf * 8 + (lane & 3) * 2;
            #pragma unroll
            for (int half = 0; half < 2; half++) {
                long long row = rbase + mf * 16 + (lane >> 2) + half * 8;
                float v0 = acc[mf][nf][half * 2 + 0];
                float v1 = acc[mf][nf][half * 2 + 1];
                if (bias) { v0 += bias[col]; v1 += bias[col + 1]; }
                if (epi == 1) { v0 = fmaxf(v0, 0.f); v1 = fmaxf(v1, 0.f); }
                else if (epi == 2) {
                    v0 = fminf(fmaxf(v0, clo), chi);
                    v1 = fminf(fmaxf(v1, clo), chi);
                }
                long long o = blockIdx.z * sC + row * N + col;
                if (C) { float2 ov = {v0, v1}; *(float2*)(C + o) = ov; }
                if (Ch) {
                    __nv_bfloat16 h0, l0, h1, l1;
                    bf16split(v0, h0, l0);
                    bf16split(v1, h1, l1);
                    __nv_bfloat162 hh(h0, h1), ll(l0, l1);
                    *(uint32_t*)(Ch + o) = *(uint32_t*)&hh;
                    *(uint32_t*)(Cl + o) = *(uint32_t*)&ll;
                }
            }
        }
    }
}

// ---------------------------------------------------------------------------
// Transpose + bf16-split convert: in [R, Cc] f32 -> out [Cc, R] bf16 hi/lo
// ---------------------------------------------------------------------------
__global__ __launch_bounds__(256)
void wtrans_kernel(const float* __restrict__ in,
                   __nv_bfloat16* __restrict__ oh, __nv_bfloat16* __restrict__ ol,
                   int R, int Cc, long long inZ, long long outZ)
{
    __shared__ float t[32][33];
    in += blockIdx.z * inZ; oh += blockIdx.z * outZ; ol += blockIdx.z * outZ;
    int r0 = blockIdx.y * 32, c0 = blockIdx.x * 32;
    int tx = threadIdx.x & 31, ty = threadIdx.x >> 5;
    #pragma unroll
    for (int i = 0; i < 4; i++)
        t[ty + i * 8][tx] = in[(long long)(r0 + ty + i * 8) * Cc + c0 + tx];
    __syncthreads();
    #pragma unroll
    for (int i = 0; i < 4; i++) {
        float v = t[tx][ty + i * 8];
        __nv_bfloat16 h, l;
        bf16split(v, h, l);
        long long o = (long long)(c0 + ty + i * 8) * R + r0 + tx;
        oh[o] = h; ol[o] = l;
    }
}

// ---------------------------------------------------------------------------
// LayerNorm over D=1024; optional residual; outputs fp32 and/or bf16 hi/lo
// ---------------------------------------------------------------------------
__global__ __launch_bounds__(256)
void ln_kernel(const float* __restrict__ X, const float* __restrict__ R,
               const float* __restrict__ g, const float* __restrict__ bta,
               float* __restrict__ outF,
               __nv_bfloat16* __restrict__ outH, __nv_bfloat16* __restrict__ outL)
{
    const int D = 1024;
    long long base = (long long)blockIdx.x * D;
    int t = threadIdx.x;

    float4 xv = *(const float4*)(X + base + t * 4);
    if (R) {
        float4 rv = *(const float4*)(R + base + t * 4);
        xv.x += rv.x; xv.y += rv.y; xv.z += rv.z; xv.w += rv.w;
    }
    float s  = xv.x + xv.y + xv.z + xv.w;
    float ss = xv.x*xv.x + xv.y*xv.y + xv.z*xv.z + xv.w*xv.w;

    __shared__ float sh[16];
    int w = t >> 5, l = t & 31;
    s  = warp_sum(s);
    ss = warp_sum(ss);
    if (l == 0) { sh[w] = s; sh[8 + w] = ss; }
    __syncthreads();
    if (t < 32) {
        float a  = (l < 8) ? sh[l]     : 0.f;
        float b2 = (l < 8) ? sh[8 + l] : 0.f;
        a  = warp_sum(a);
        b2 = warp_sum(b2);
        if (l == 0) { sh[0] = a; sh[1] = b2; }
    }
    __syncthreads();

    float mu  = sh[0] * (1.f / 1024.f);
    float var = sh[1] * (1.f / 1024.f) - mu * mu;
    var = fmaxf(var, 0.f);
    float rs = rsqrtf(var + EPS);

    float4 gv = *(const float4*)(g   + t * 4);
    float4 bv = *(const float4*)(bta + t * 4);
    float4 o;
    o.x = (xv.x - mu) * rs * gv.x + bv.x;
    o.y = (xv.y - mu) * rs * gv.y + bv.y;
    o.z = (xv.z - mu) * rs * gv.z + bv.z;
    o.w = (xv.w - mu) * rs * gv.w + bv.w;
    if (outF) *(float4*)(outF + base + t * 4) = o;
    if (outH) {
        __nv_bfloat16 h0,l0,h1,l1,h2,l2,h3,l3;
        bf16split(o.x, h0, l0); bf16split(o.y, h1, l1);
        bf16split(o.z, h2, l2); bf16split(o.w, h3, l3);
        __nv_bfloat162 ha(h0, h1), hb(h2, h3), la(l0, l1), lb(l2, l3);
        uint2 hv = {*(uint32_t*)&ha, *(uint32_t*)&hb};
        uint2 lv = {*(uint32_t*)&la, *(uint32_t*)&lb};
        *(uint2*)(outH + base + t * 4) = hv;
        *(uint2*)(outL + base + t * 4) = lv;
    }
}

// ---------------------------------------------------------------------------
// Masked softmax: reads fp32 scores, writes bf16 hi/lo attn probs
// ---------------------------------------------------------------------------
__global__ __launch_bounds__(256)
void softmax_kernel(const float* __restrict__ scores, const int* __restrict__ mask,
                    const float* __restrict__ scale,
                    __nv_bfloat16* __restrict__ outH, __nv_bfloat16* __restrict__ outL)
{
    const int S = 1024;
    int b = blockIdx.y;
    long long base = (((long long)b * S) + blockIdx.x) * S;
    int t = threadIdx.x;
    float sc = scale[0];

    float4 v = *(const float4*)(scores + base + t * 4);
    const int4 mv = *(const int4*)(mask + b * S + t * 4);
    float e0 = (mv.x != 0) ? v.x * sc : -1e9f;
    float e1 = (mv.y != 0) ? v.y * sc : -1e9f;
    float e2 = (mv.z != 0) ? v.z * sc : -1e9f;
    float e3 = (mv.w != 0) ? v.w * sc : -1e9f;

    __shared__ float sh[8];
    int w = t >> 5, l = t & 31;

    float m = fmaxf(fmaxf(e0, e1), fmaxf(e2, e3));
    m = warp_max(m);
    if (l == 0) sh[w] = m;
    __syncthreads();
    if (t < 32) {
        float a = (l < 8) ? sh[l] : -3.4e38f;
        a = warp_max(a);
        if (l == 0) sh[0] = a;
    }
    __syncthreads();
    m = sh[0];
    __syncthreads();

    float x0 = __expf(e0 - m), x1 = __expf(e1 - m);
    float x2 = __expf(e2 - m), x3 = __expf(e3 - m);
    float sum = x0 + x1 + x2 + x3;
    sum = warp_sum(sum);
    if (l == 0) sh[w] = sum;
    __syncthreads();
    if (t < 32) {
        float a = (l < 8) ? sh[l] : 0.f;
        a = warp_sum(a);
        if (l == 0) sh[0] = a;
    }
    __syncthreads();
    float inv = 1.f / sh[0];

    float p0 = x0 * inv, p1 = x1 * inv, p2 = x2 * inv, p3 = x3 * inv;
    __nv_bfloat16 h0,l0,h1,l1,h2,l2,h3,l3;
    bf16split(p0, h0, l0); bf16split(p1, h1, l1);
    bf16split(p2, h2, l2); bf16split(p3, h3, l3);
    __nv_bfloat162 ha(h0, h1), hb(h2, h3), la(l0, l1), lb(l2, l3);
    uint2 hv = {*(uint32_t*)&ha, *(uint32_t*)&hb};
    uint2 lv = {*(uint32_t*)&la, *(uint32_t*)&lb};
    *(uint2*)(outH + base + t * 4) = hv;
    *(uint2*)(outL + base + t * 4) = lv;
}

// ---------------------------------------------------------------------------
// Launch
// ---------------------------------------------------------------------------
static void* sym(const void* s) { void* p = nullptr; cudaGetSymbolAddress(&p, s); return p; }

extern "C" void kernel_launch(void* const* d_in, const int* in_sizes, int n_in,
                              void* d_out, int out_size)
{
    const float* x       = (const float*)d_in[0];
    const int*   mask    = (const int*)  d_in[1];
    const float* ln_in_g = (const float*)d_in[2];
    const float* ln_in_b = (const float*)d_in[3];
    const float* W_mlp   = (const float*)d_in[4];
    const float* b_mlp   = (const float*)d_in[5];
    const float* W_proj  = (const float*)d_in[6];
    const float* b_proj  = (const float*)d_in[7];
    const float* scale   = (const float*)d_in[8];
    const float* Wq      = (const float*)d_in[9];
    const float* bq      = (const float*)d_in[10];
    const float* Wk      = (const float*)d_in[11];
    const float* bk      = (const float*)d_in[12];
    const float* Wv      = (const float*)d_in[13];
    const float* bv      = (const float*)d_in[14];
    const float* ln1_g   = (const float*)d_in[15];
    const float* ln1_b   = (const float*)d_in[16];
    const float* W_f1    = (const float*)d_in[17];
    const float* b_f1    = (const float*)d_in[18];
    const float* W_f2    = (const float*)d_in[19];
    const float* b_f2    = (const float*)d_in[20];
    const float* ln2_g   = (const float*)d_in[21];
    const float* ln2_b   = (const float*)d_in[22];
    const float* lno_g   = (const float*)d_in[23];
    const float* lno_b   = (const float*)d_in[24];
    float* out = (float*)d_out;

    float* xp = (float*)sym(g_xp);
    float* v  = (float*)sym(g_v);
    float* sc = (float*)sym(g_sc);
    float* ao = (float*)sym(g_ao);
    float* x1 = (float*)sym(g_x1);
    float* x2 = xp;   // xp dead after step 8; reuse as x2

    __nv_bfloat16 *xln_h=(__nv_bfloat16*)sym(g_xln_h), *xln_l=(__nv_bfloat16*)sym(g_xln_l);
    __nv_bfloat16 *big_h=(__nv_bfloat16*)sym(g_big_h), *big_l=(__nv_bfloat16*)sym(g_big_l);
    __nv_bfloat16 *xp_h =(__nv_bfloat16*)sym(g_xp_h),  *xp_l =(__nv_bfloat16*)sym(g_xp_l);
    __nv_bfloat16 *q_h  =(__nv_bfloat16*)sym(g_q_h),   *q_l  =(__nv_bfloat16*)sym(g_q_l);
    __nv_bfloat16 *k_h  =(__nv_bfloat16*)sym(g_k_h),   *k_l  =(__nv_bfloat16*)sym(g_k_l);
    __nv_bfloat16 *vt_h =(__nv_bfloat16*)sym(g_vt_h),  *vt_l =(__nv_bfloat16*)sym(g_vt_l);
    __nv_bfloat16 *at_h =(__nv_bfloat16*)sym(g_at_h),  *at_l =(__nv_bfloat16*)sym(g_at_l);
    __nv_bfloat16 *x1_h =(__nv_bfloat16*)sym(g_x1_h),  *x1_l =(__nv_bfloat16*)sym(g_x1_l);

    __nv_bfloat16 *wmlp_h=(__nv_bfloat16*)sym(g_wmlp_h), *wmlp_l=(__nv_bfloat16*)sym(g_wmlp_l);
    __nv_bfloat16 *wprj_h=(__nv_bfloat16*)sym(g_wprj_h), *wprj_l=(__nv_bfloat16*)sym(g_wprj_l);
    __nv_bfloat16 *wq_h=(__nv_bfloat16*)sym(g_wq_h), *wq_l=(__nv_bfloat16*)sym(g_wq_l);
    __nv_bfloat16 *wk_h=(__nv_bfloat16*)sym(g_wk_h), *wk_l=(__nv_bfloat16*)sym(g_wk_l);
    __nv_bfloat16 *wv_h=(__nv_bfloat16*)sym(g_wv_h), *wv_l=(__nv_bfloat16*)sym(g_wv_l);
    __nv_bfloat16 *wf1_h=(__nv_bfloat16*)sym(g_wf1_h), *wf1_l=(__nv_bfloat16*)sym(g_wf1_l);
    __nv_bfloat16 *wf2_h=(__nv_bfloat16*)sym(g_wf2_h), *wf2_l=(__nv_bfloat16*)sym(g_wf2_l);

    cudaFuncSetAttribute(tc_gemm, cudaFuncAttributeMaxDynamicSharedMemorySize, SMEM_DYN);

    const dim3 blk(256);
    const long long SD  = (long long)S_ * DOUT;   // per-batch [S,D] stride
    const long long SS  = (long long)S_ * S_;     // per-batch [S,S] stride

    // ---- weight transpose+split (W[K,N] -> [N,K] hi/lo)
    wtrans_kernel<<<dim3(DH/32,  DIN/32),  blk>>>(W_mlp,  wmlp_h, wmlp_l, DIN, DH,  0, 0);
    wtrans_kernel<<<dim3(DOUT/32,DH/32),   blk>>>(W_proj, wprj_h, wprj_l, DH,  DOUT,0, 0);
    wtrans_kernel<<<dim3(DOUT/32,DOUT/32), blk>>>(Wq,     wq_h,   wq_l,   DOUT,DOUT,0, 0);
    wtrans_kernel<<<dim3(DOUT/32,DOUT/32), blk>>>(Wk,     wk_h,   wk_l,   DOUT,DOUT,0, 0);
    wtrans_kernel<<<dim3(DOUT/32,DOUT/32), blk>>>(Wv,     wv_h,   wv_l,   DOUT,DOUT,0, 0);
    wtrans_kernel<<<dim3(DH/32,  DOUT/32), blk>>>(W_f1,   wf1_h,  wf1_l,  DOUT,DH,  0, 0);
    wtrans_kernel<<<dim3(DOUT/32,DH/32),   blk>>>(W_f2,   wf2_h,  wf2_l,  DH,  DOUT,0, 0);

    // 1. x_ln = LN(x) -> hi/lo only
    ln_kernel<<<TOK, blk>>>(x, nullptr, ln_in_g, ln_in_b, nullptr, xln_h, xln_l);

    // 2. h = relu(x_ln @ W_mlp + b) -> hi/lo only
    tc_gemm<<<dim3(DH/GBN, TOK/GBM), blk, SMEM_DYN>>>(
        xln_h, xln_l, wmlp_h, wmlp_l, b_mlp, nullptr, big_h, big_l,
        DIN, DH, 0, 0, 0, 1, 0.f, 0.f);

    // 3. xp = clip(h @ W_proj + b, -100, 100) -> fp32 + hi/lo
    tc_gemm<<<dim3(DOUT/GBN, TOK/GBM), blk, SMEM_DYN>>>(
        big_h, big_l, wprj_h, wprj_l, b_proj, xp, xp_h, xp_l,
        DH, DOUT, 0, 0, 0, 2, -100.f, 100.f);

    // 4. q/k/v
    tc_gemm<<<dim3(DOUT/GBN, TOK/GBM), blk, SMEM_DYN>>>(
        xp_h, xp_l, wq_h, wq_l, bq, nullptr, q_h, q_l, DOUT, DOUT, 0, 0, 0, 0, 0.f, 0.f);
    tc_gemm<<<dim3(DOUT/GBN, TOK/GBM), blk, SMEM_DYN>>>(
        xp_h, xp_l, wk_h, wk_l, bk, nullptr, k_h, k_l, DOUT, DOUT, 0, 0, 0, 0, 0.f, 0.f);
    tc_gemm<<<dim3(DOUT/GBN, TOK/GBM), blk, SMEM_DYN>>>(
        xp_h, xp_l, wv_h, wv_l, bv, v, nullptr, nullptr, DOUT, DOUT, 0, 0, 0, 0, 0.f, 0.f);

    // 4b. v^T per batch -> [D,S] hi/lo
    wtrans_kernel<<<dim3(DOUT/32, S_/32, B_), blk>>>(v, vt_h, vt_l, S_, DOUT, SD, SD);

    // 5. scores[b] = q[b] @ k[b]^T (fp32)
    tc_gemm<<<dim3(S_/GBN, S_/GBM, B_), blk, SMEM_DYN>>>(
        q_h, q_l, k_h, k_l, nullptr, sc, nullptr, nullptr,
        DOUT, S_, SD, SD, SS, 0, 0.f, 0.f);

    // 6. masked softmax -> attn hi/lo
    softmax_kernel<<<dim3(S_, B_), blk>>>(sc, mask, scale, at_h, at_l);

    // 7. ao[b] = attn[b] @ v[b]  (B operand = v^T [D,S])
    tc_gemm<<<dim3(DOUT/GBN, S_/GBM, B_), blk, SMEM_DYN>>>(
        at_h, at_l, vt_h, vt_l, nullptr, ao, nullptr, nullptr,
        S_, DOUT, SS, SD, SD, 0, 0.f, 0.f);

    // 8. x1 = LN(xp + ao) -> fp32 + hi/lo
    ln_kernel<<<TOK, blk>>>(xp, ao, ln1_g, ln1_b, x1, x1_h, x1_l);

    // 9. ffn_h = relu(x1 @ W_f1 + b) -> hi/lo (reuse big)
    tc_gemm<<<dim3(DH/GBN, TOK/GBM), blk, SMEM_DYN>>>(
        x1_h, x1_l, wf1_h, wf1_l, b_f1, nullptr, big_h, big_l,
        DOUT, DH, 0, 0, 0, 1, 0.f, 0.f);

    // 10. ffn_o = ffn_h @ W_f2 + b -> fp32 (reuse v)
    tc_gemm<<<dim3(DOUT/GBN, TOK/GBM), blk, SMEM_DYN>>>(
        big_h, big_l, wf2_h, wf2_l, b_f2, v, nullptr, nullptr,
        DH, DOUT, 0, 0, 0, 0, 0.f, 0.f);

    // 11. x2 = LN(x1 + ffn_o)   (x2 aliases xp; xp consumed before this point)
    ln_kernel<<<TOK, blk>>>(x1, v, ln2_g, ln2_b, x2, nullptr, nullptr);

    // 12. out = LN(x2)
    ln_kernel<<<TOK, blk>>>(x2, nullptr, lno_g, lno_b, out, nullptr, nullptr);
}